// round 15
// baseline (speedup 1.0000x reference)
#include <cuda_runtime.h>
#include <cuda_bf16.h>
#include <cstdint>

#define N_NODES   100000
#define N_EDGES   625000
#define HIDDEN    128
#define INPUT_DIM 28
#define N_LAYERS  4
#define NUM_GRAPHS 512
#define GRID_M    ((N_NODES + 127) / 128)
#define SCAN_BLKS ((N_NODES + 1023) / 1024)   // 98

// Scratch (device globals; allocation inside kernel_launch is forbidden)
// z state lives in bf16 (halves gather traffic; agg still sums in fp32)
__device__ __nv_bfloat16 d_zA[N_NODES * HIDDEN];
__device__ __nv_bfloat16 d_zB[N_NODES * HIDDEN];
__device__ float d_g[NUM_GRAPHS * HIDDEN];
__device__ int   d_gcnt[NUM_GRAPHS];
// Gathered A tiles (plain bf16), pre-swizzled in GEMM smem layout:
// [tile][chunk(2)][swz(row*128 + col*2)] bf16
__device__ __nv_bfloat16 d_aggH[GRID_M * 128 * HIDDEN];
// Composite conv weights, transposed + bf16 hi/lo split: [4 mats][n=128][k=128]
__device__ __nv_bfloat16 d_WBhi[4 * HIDDEN * HIDDEN];
__device__ __nv_bfloat16 d_WBlo[4 * HIDDEN * HIDDEN];
__device__ float d_cvec[4 * HIDDEN];   // c_l = b2_{l-1} @ W1_l (c_0 = 0)
__device__ float d_Ep[INPUT_DIM * HIDDEN];   // E' = node_emb @ W1_0 (fp32)
// CSR (by dst) machinery
__device__ int d_deg[N_NODES];
__device__ int d_rowptr[N_NODES + 1];
__device__ int d_wpos[N_NODES];
__device__ int d_csr_src[N_EDGES];
__device__ int d_bsum[SCAN_BLKS];
__device__ volatile int d_bflag[SCAN_BLKS];

__device__ __forceinline__ __nv_bfloat16* sel_buf(int s) {
    return s == 0 ? d_zA : d_zB;
}

__device__ __forceinline__ uint32_t smem_u32(const void* p) {
    uint32_t a;
    asm("{ .reg .u64 t; cvta.to.shared.u64 t, %1; cvt.u32.u64 %0, t; }"
        : "=r"(a) : "l"(p));
    return a;
}
// SW128-style swizzle: XOR bits[9:7] into bits[6:4]. Apply to FULL byte offset.
__device__ __forceinline__ uint32_t swz(uint32_t b) {
    return b ^ ((b >> 3) & 0x70);
}
// unpack 4 bf16 (uint2) and accumulate into float4
__device__ __forceinline__ void acc_bf4(float4& a, uint2 u) {
    __nv_bfloat162 p0 = *reinterpret_cast<__nv_bfloat162*>(&u.x);
    __nv_bfloat162 p1 = *reinterpret_cast<__nv_bfloat162*>(&u.y);
    float2 f0 = __bfloat1622float2(p0);
    float2 f1 = __bfloat1622float2(p1);
    a.x += f0.x; a.y += f0.y; a.z += f1.x; a.w += f1.y;
}
__device__ __forceinline__ uint2 pack_bf4(float4 v) {
    uint2 u;
    __nv_bfloat162 p0 = __float22bfloat162_rn(make_float2(v.x, v.y));
    __nv_bfloat162 p1 = __float22bfloat162_rn(make_float2(v.z, v.w));
    u.x = *reinterpret_cast<uint32_t*>(&p0);
    u.y = *reinterpret_cast<uint32_t*>(&p1);
    return u;
}

// ---------------------------------------------------------------------------
// Fused prep: all zeroing + composite weights + cvec + E' table, ONE kernel.
// ---------------------------------------------------------------------------
__global__ void prep_all_kernel(const float* __restrict__ node_emb,
                                const float* __restrict__ W1,
                                const float* __restrict__ W2,
                                const float* __restrict__ b2) {
    int t = blockIdx.x * blockDim.x + threadIdx.x;
    if (t < N_NODES) d_deg[t] = 0;
    if (t < NUM_GRAPHS * HIDDEN) d_g[t] = 0.f;
    if (t < NUM_GRAPHS) d_gcnt[t] = 0;
    if (t < SCAN_BLKS) d_bflag[t] = 0;

    if (t < 49152) {
        int l = 1 + (t >> 14);
        int idx = t & 16383;
        int n = idx & 127, k = idx >> 7;
        const float* W2r = W2 + (l - 1) * HIDDEN * HIDDEN + k * HIDDEN;
        const float* W1m = W1 + l * HIDDEN * HIDDEN;
        float s = 0.f;
#pragma unroll 8
        for (int j = 0; j < HIDDEN; j++) s = fmaf(W2r[j], W1m[j * HIDDEN + n], s);
        __nv_bfloat16 hi = __float2bfloat16(s);
        d_WBhi[l * 16384 + n * 128 + k] = hi;
        d_WBlo[l * 16384 + n * 128 + k] = __float2bfloat16(s - __bfloat162float(hi));
    } else if (t < 49664) {
        int u = t - 49152;
        int l = u >> 7, n = u & 127;
        float s = 0.f;
        if (l > 0) {
            const float* b2r = b2 + (l - 1) * HIDDEN;
            const float* W1m = W1 + l * HIDDEN * HIDDEN;
#pragma unroll 8
            for (int j = 0; j < HIDDEN; j++) s = fmaf(b2r[j], W1m[j * HIDDEN + n], s);
        }
        d_cvec[u] = s;
    } else if (t < 49664 + INPUT_DIM * HIDDEN) {
        int u = t - 49664;
        int v = u >> 7, n = u & 127;
        const float* er = node_emb + v * HIDDEN;
        float s = 0.f;
#pragma unroll 8
        for (int k = 0; k < HIDDEN; k++) s = fmaf(er[k], W1[k * HIDDEN + n], s);
        d_Ep[u] = s;
    }
}

// ---------------------------------------------------------------------------
// Layer 0 (tablified): z0 = relu(E'[x_i] + sum E'[x_src] + b1_0) -> bf16.
// ---------------------------------------------------------------------------
__global__ void layer0_kernel(const int* __restrict__ x,
                              const float* __restrict__ b1) {
    int t = blockIdx.x * blockDim.x + threadIdx.x;
    int node = t >> 5;
    if (node >= N_NODES) return;
    int lane = t & 31;
    int c4 = lane << 2;

    float4 acc = *(const float4*)&d_Ep[__ldg(&x[node]) * 128 + c4];
    int beg = __ldg(&d_rowptr[node]);
    int end = __ldg(&d_rowptr[node + 1]);
    int j = beg;
    for (; j + 4 <= end; j += 4) {
        int s0 = __ldg(&x[__ldg(&d_csr_src[j + 0])]);
        int s1 = __ldg(&x[__ldg(&d_csr_src[j + 1])]);
        int s2 = __ldg(&x[__ldg(&d_csr_src[j + 2])]);
        int s3 = __ldg(&x[__ldg(&d_csr_src[j + 3])]);
        float4 v0 = *(const float4*)&d_Ep[s0 * 128 + c4];
        float4 v1 = *(const float4*)&d_Ep[s1 * 128 + c4];
        float4 v2 = *(const float4*)&d_Ep[s2 * 128 + c4];
        float4 v3 = *(const float4*)&d_Ep[s3 * 128 + c4];
        acc.x += (v0.x + v1.x) + (v2.x + v3.x);
        acc.y += (v0.y + v1.y) + (v2.y + v3.y);
        acc.z += (v0.z + v1.z) + (v2.z + v3.z);
        acc.w += (v0.w + v1.w) + (v2.w + v3.w);
    }
    for (; j < end; j++) {
        int s = __ldg(&x[__ldg(&d_csr_src[j])]);
        float4 v = *(const float4*)&d_Ep[s * 128 + c4];
        acc.x += v.x; acc.y += v.y; acc.z += v.z; acc.w += v.w;
    }
    float4 bb = *(const float4*)&b1[c4];
    float4 o;
    o.x = fmaxf(acc.x + bb.x, 0.f);
    o.y = fmaxf(acc.y + bb.y, 0.f);
    o.z = fmaxf(acc.z + bb.z, 0.f);
    o.w = fmaxf(acc.w + bb.w, 0.f);
    *(uint2*)&d_zA[node * 128 + c4] = pack_bf4(o);
}

// ---------------------------------------------------------------------------
// Gather: one warp per node. agg = z[node] + sum z[src] (bf16 in, fp32 acc);
// round to bf16; write d_aggH in the GEMM smem tile layout.
// Rows beyond N_NODES (tail tile) are zero-filled. COUNT also tallies d_gcnt.
// ---------------------------------------------------------------------------
template <bool COUNT>
__global__ void gather_kernel(int insel, const int* __restrict__ batch) {
    int t = blockIdx.x * blockDim.x + threadIdx.x;
    int node = t >> 5;
    if (node >= GRID_M * 128) return;
    int lane = t & 31;
    const __nv_bfloat16* __restrict__ SRC = sel_buf(insel);
    int c4 = lane << 2;

    float4 acc = make_float4(0.f, 0.f, 0.f, 0.f);
    if (node < N_NODES) {
        if (COUNT && lane == 0) atomicAdd(&d_gcnt[__ldg(&batch[node])], 1);
        acc_bf4(acc, *(const uint2*)&SRC[node * 128 + c4]);
        int beg = __ldg(&d_rowptr[node]);
        int end = __ldg(&d_rowptr[node + 1]);
        int j = beg;
        for (; j + 4 <= end; j += 4) {
            int s0 = __ldg(&d_csr_src[j + 0]);
            int s1 = __ldg(&d_csr_src[j + 1]);
            int s2 = __ldg(&d_csr_src[j + 2]);
            int s3 = __ldg(&d_csr_src[j + 3]);
            uint2 u0 = *(const uint2*)&SRC[s0 * 128 + c4];
            uint2 u1 = *(const uint2*)&SRC[s1 * 128 + c4];
            uint2 u2 = *(const uint2*)&SRC[s2 * 128 + c4];
            uint2 u3 = *(const uint2*)&SRC[s3 * 128 + c4];
            acc_bf4(acc, u0); acc_bf4(acc, u1);
            acc_bf4(acc, u2); acc_bf4(acc, u3);
        }
        for (; j < end; j++) {
            int s = __ldg(&d_csr_src[j]);
            acc_bf4(acc, *(const uint2*)&SRC[s * 128 + c4]);
        }
    }
    int tile = node >> 7, row = node & 127;
    uint32_t off = (uint32_t)tile * 32768 + (uint32_t)(c4 >> 6) * 16384 +
                   swz((uint32_t)(row * 128) + (uint32_t)((c4 & 63) << 1));
    *(uint2*)((char*)d_aggH + off) = pack_bf4(acc);
}

// ---------------------------------------------------------------------------
// MMA helpers
// ---------------------------------------------------------------------------
__device__ __forceinline__ void mma_bf16(float* c, const uint32_t* a,
                                         const uint32_t* b) {
    asm volatile(
        "mma.sync.aligned.m16n8k16.row.col.f32.bf16.bf16.f32 "
        "{%0,%1,%2,%3}, {%4,%5,%6,%7}, {%8,%9}, {%0,%1,%2,%3};"
        : "+f"(c[0]), "+f"(c[1]), "+f"(c[2]), "+f"(c[3])
        : "r"(a[0]), "r"(a[1]), "r"(a[2]), "r"(a[3]), "r"(b[0]), "r"(b[1]));
}
#define LDSM_X4(r, addr) \
    asm volatile("ldmatrix.sync.aligned.m8n8.x4.shared.b16 {%0,%1,%2,%3}, [%4];" \
                 : "=r"((r)[0]), "=r"((r)[1]), "=r"((r)[2]), "=r"((r)[3]) \
                 : "r"(addr))
#define LDSM_X2(r, addr) \
    asm volatile("ldmatrix.sync.aligned.m8n8.x2.shared.b16 {%0,%1}, [%2];" \
                 : "=r"((r)[0]), "=r"((r)[1]) : "r"(addr))

// smem: A (2 chunks, 32KB) at 0, W-hi (full, 32KB) at 32K, W-lo at 64K. 96KB.
#define SW_HI 32768
#define SW_LO 65536
#define SMEMB 98304

// ---------------------------------------------------------------------------
// GEMM: y = relu(A @ WT + deg'*c + b1).  A plain bf16; W split hi/lo (2 terms).
// Full W resident in smem -> ONE __syncthreads in the whole kernel.
// POOL=false: y -> zout (bf16).  POOL=true: y pooled into d_g via red.add.
// CTA: 128 rows, 256 threads (8 warps, 32x64 tiles).
// ---------------------------------------------------------------------------
template <bool POOL>
__global__ __launch_bounds__(256, 2) void gemm_kernel(
    int outsel, int widx, const float* __restrict__ b1,
    const int* __restrict__ batch) {
    __nv_bfloat16* __restrict__ zout = sel_buf(outsel);
    const float* __restrict__ cvec = d_cvec + widx * HIDDEN;
    const __nv_bfloat16* __restrict__ Whi = d_WBhi + widx * 16384;
    const __nv_bfloat16* __restrict__ Wlo = d_WBlo + widx * 16384;

    extern __shared__ char sm[];
    uint32_t sbase = smem_u32(sm);

    int tid = threadIdx.x;
    int lane = tid & 31;
    int wid = tid >> 5;
    int wm = (wid & 3) * 32;
    int wn = (wid >> 2) * 64;
    int bm = blockIdx.x * 128;

    // ---- stage A (identity copy, pre-swizzled) + full W (hi/lo, chunked) ----
    {
        const uint4* ga = (const uint4*)(d_aggH + (size_t)blockIdx.x * 16384);
#pragma unroll
        for (int it = 0; it < 8; it++) {
            int idx = it * 256 + tid;
            ((uint4*)sm)[idx] = ga[idx];
        }
#pragma unroll
        for (int it = 0; it < 8; it++) {        // 2048 uint4 tasks per W matrix
            int idx = it * 256 + tid;
            int ch = idx >> 10;                 // k-chunk
            int row = (idx & 1023) >> 3;        // n row
            int c8 = (idx & 7) * 8;             // k offset in chunk
            uint32_t off = (uint32_t)ch * 16384 +
                           swz((uint32_t)(row * 128 + c8 * 2));
            *(uint4*)(sm + SW_HI + off) =
                *(const uint4*)&Whi[row * 128 + ch * 64 + c8];
            *(uint4*)(sm + SW_LO + off) =
                *(const uint4*)&Wlo[row * 128 + ch * 64 + c8];
        }
    }
    __syncthreads();

    float acc[2][8][4];
#pragma unroll
    for (int i = 0; i < 2; i++)
#pragma unroll
        for (int j = 0; j < 8; j++)
#pragma unroll
            for (int q = 0; q < 4; q++) acc[i][j][q] = 0.f;

#pragma unroll
    for (int ks = 0; ks < 8; ks++) {
        uint32_t chb = (uint32_t)(ks >> 2) * 16384;
        int kl = (ks & 3) * 16;
        uint32_t ahi[2][4];
#pragma unroll
        for (int mi = 0; mi < 2; mi++) {
            int r = wm + mi * 16 + (lane & 15);
            int kc = kl + (lane >> 4) * 8;
            uint32_t ad = sbase + chb + swz((uint32_t)(r * 128 + kc * 2));
            LDSM_X4(ahi[mi], ad);
        }
#pragma unroll
        for (int nj = 0; nj < 8; nj++) {
            int nr = wn + nj * 8 + (lane & 7);
            int kc = kl + ((lane >> 3) & 1) * 8;
            uint32_t bd = sbase + SW_HI + chb +
                          swz((uint32_t)(nr * 128 + kc * 2));
            uint32_t bh[2], bl[2];
            LDSM_X2(bh, bd);
            LDSM_X2(bl, bd + (SW_LO - SW_HI));
#pragma unroll
            for (int mi = 0; mi < 2; mi++) {
                mma_bf16(acc[mi][nj], ahi[mi], bh);
                mma_bf16(acc[mi][nj], ahi[mi], bl);
            }
        }
    }

    // ---- epilogue: y = relu(acc + deg'*c + b1) -> zout(bf16) OR pooled d_g ----
    int g = lane >> 2, tg = lane & 3;
    float degp[2][2];
    int gidx[2][2];
#pragma unroll
    for (int mi = 0; mi < 2; mi++)
#pragma unroll
        for (int h = 0; h < 2; h++) {
            int row = bm + wm + mi * 16 + g + h * 8;
            bool ok = row < N_NODES;
            degp[mi][h] = ok
                ? (float)(__ldg(&d_rowptr[row + 1]) - __ldg(&d_rowptr[row]) + 1)
                : 0.f;
            if (POOL) gidx[mi][h] = ok ? __ldg(&batch[row]) : 0;
        }
#pragma unroll
    for (int nj = 0; nj < 8; nj++) {
        int col = wn + nj * 8 + tg * 2;
        float2 bb = *(const float2*)&b1[col];
        float2 cv = *(const float2*)&cvec[col];
#pragma unroll
        for (int mi = 0; mi < 2; mi++) {
            int r0 = bm + wm + mi * 16 + g;
            float2 o0, o1;
            o0.x = fmaxf(acc[mi][nj][0] + degp[mi][0] * cv.x + bb.x, 0.f);
            o0.y = fmaxf(acc[mi][nj][1] + degp[mi][0] * cv.y + bb.y, 0.f);
            o1.x = fmaxf(acc[mi][nj][2] + degp[mi][1] * cv.x + bb.x, 0.f);
            o1.y = fmaxf(acc[mi][nj][3] + degp[mi][1] * cv.y + bb.y, 0.f);
            if (POOL) {
                if (r0 < N_NODES) {
                    float* p = &d_g[gidx[mi][0] * 128 + col];
                    asm volatile("red.global.add.v2.f32 [%0], {%1,%2};"
                                 :: "l"(p), "f"(o0.x), "f"(o0.y) : "memory");
                }
                if (r0 + 8 < N_NODES) {
                    float* p = &d_g[gidx[mi][1] * 128 + col];
                    asm volatile("red.global.add.v2.f32 [%0], {%1,%2};"
                                 :: "l"(p), "f"(o1.x), "f"(o1.y) : "memory");
                }
            } else {
                if (r0 < N_NODES) {
                    __nv_bfloat162 p =
                        __float22bfloat162_rn(make_float2(o0.x, o0.y));
                    *(uint32_t*)&zout[r0 * 128 + col] =
                        *reinterpret_cast<uint32_t*>(&p);
                }
                if (r0 + 8 < N_NODES) {
                    __nv_bfloat162 p =
                        __float22bfloat162_rn(make_float2(o1.x, o1.y));
                    *(uint32_t*)&zout[(r0 + 8) * 128 + col] =
                        *reinterpret_cast<uint32_t*>(&p);
                }
            }
        }
    }
}

// ---------------------------------------------------------------------------
// CSR build (by dst): histogram -> single-pass scan (lookback) -> fill
// ---------------------------------------------------------------------------
__global__ void hist_kernel(const int* __restrict__ dst) {
    int e = blockIdx.x * blockDim.x + threadIdx.x;
    if (e < N_EDGES) atomicAdd(&d_deg[dst[e]], 1);
}
// Single-pass scan: all SCAN_BLKS (98 <= 148 SMs) blocks are co-resident, so
// publish-aggregate + wait-for-all-predecessors cannot deadlock.
__global__ __launch_bounds__(1024) void scan_kernel() {
    __shared__ int ws[32];
    __shared__ int sbase_sh;
    int i = blockIdx.x * 1024 + threadIdx.x;
    int v = (i < N_NODES) ? d_deg[i] : 0;
    int lane = threadIdx.x & 31, w = threadIdx.x >> 5;
    // block-local inclusive scan
    int x = v;
#pragma unroll
    for (int o = 1; o < 32; o <<= 1) {
        int y = __shfl_up_sync(0xffffffffu, x, o);
        if (lane >= o) x += y;
    }
    if (lane == 31) ws[w] = x;
    __syncthreads();
    if (w == 0) {
        int y = (lane < 32) ? ws[lane] : 0;
#pragma unroll
        for (int o = 1; o < 32; o <<= 1) {
            int z = __shfl_up_sync(0xffffffffu, y, o);
            if (lane >= o) y += z;
        }
        ws[lane] = y;
    }
    __syncthreads();
    int incl = x + (w ? ws[w - 1] : 0);
    // thread 1023 holds the block total -> publish aggregate
    if (threadIdx.x == 1023) {
        d_bsum[blockIdx.x] = incl;
        __threadfence();
        d_bflag[blockIdx.x] = 1;
    }
    // thread 0: sum aggregates of all preceding blocks (spin until published)
    if (threadIdx.x == 0) {
        int r = 0;
        for (int q = 0; q < blockIdx.x; q++) {
            while (d_bflag[q] == 0) { }
            r += d_bsum[q];
        }
        sbase_sh = r;
    }
    __syncthreads();
    int excl = sbase_sh + incl - v;
    if (i < N_NODES) {
        d_rowptr[i] = excl;
        d_wpos[i] = excl;
        if (i == N_NODES - 1) d_rowptr[N_NODES] = excl + v;
    }
}
__global__ void fill_kernel(const int* __restrict__ src,
                            const int* __restrict__ dst) {
    int e = blockIdx.x * blockDim.x + threadIdx.x;
    if (e >= N_EDGES) return;
    int p = atomicAdd(&d_wpos[dst[e]], 1);
    d_csr_src[p] = src[e];
}

// ---------------------------------------------------------------------------
// Head: gh = gpool @ W2_3 + cnt*b2_3 ; then 128->64(relu)->32(relu)->1
// ---------------------------------------------------------------------------
__global__ __launch_bounds__(128) void head_kernel(
    const float* __restrict__ W2c, const float* __restrict__ b2c,
    const float* __restrict__ W1, const float* __restrict__ b1,
    const float* __restrict__ W2, const float* __restrict__ b2,
    const float* __restrict__ W3, const float* __restrict__ b3,
    float* __restrict__ out) {
    __shared__ float sg[128];
    __shared__ float gh[128];
    __shared__ float s1[64];
    int g = blockIdx.x;
    int tid = threadIdx.x;

    sg[tid] = d_g[g * 128 + tid];
    __syncthreads();
    float cnt = (float)d_gcnt[g];

    float a = cnt * __ldg(&b2c[tid]);
#pragma unroll 8
    for (int k = 0; k < 128; k++) a = fmaf(sg[k], W2c[k * 128 + tid], a);
    gh[tid] = a;
    __syncthreads();

    if (tid < 64) {
        float acc = __ldg(&b1[tid]);
#pragma unroll 8
        for (int k = 0; k < 128; k++) acc = fmaf(gh[k], W1[k * 64 + tid], acc);
        s1[tid] = fmaxf(acc, 0.f);
    }
    __syncthreads();

    if (tid < 32) {
        float a2 = __ldg(&b2[tid]);
#pragma unroll 8
        for (int k = 0; k < 64; k++) a2 = fmaf(s1[k], W2[k * 32 + tid], a2);
        a2 = fmaxf(a2, 0.f);
        float t3 = a2 * __ldg(&W3[tid]);
#pragma unroll
        for (int o = 16; o; o >>= 1) t3 += __shfl_down_sync(0xffffffffu, t3, o);
        if (tid == 0) out[g] = t3 + __ldg(&b3[0]);
    }
}

// ---------------------------------------------------------------------------
extern "C" void kernel_launch(void* const* d_in, const int* in_sizes, int n_in,
                              void* d_out, int out_size) {
    const int*   x        = (const int*)d_in[0];
    const int*   edge_idx = (const int*)d_in[1];
    const int*   src      = edge_idx;
    const int*   dst      = edge_idx + N_EDGES;
    const int*   batch    = (const int*)d_in[3];
    const float* node_emb = (const float*)d_in[4];
    // d_in[2] (edge_attr) and d_in[5] (edge_emb) are dead in the reference.
    const float* conv_W1  = (const float*)d_in[6];
    const float* conv_b1  = (const float*)d_in[7];
    const float* conv_W2  = (const float*)d_in[8];
    const float* conv_b2  = (const float*)d_in[9];
    const float* mlp_W1   = (const float*)d_in[10];
    const float* mlp_b1   = (const float*)d_in[11];
    const float* mlp_W2   = (const float*)d_in[12];
    const float* mlp_b2   = (const float*)d_in[13];
    const float* mlp_W3   = (const float*)d_in[14];
    const float* mlp_b3   = (const float*)d_in[15];
    float* out = (float*)d_out;

    cudaFuncSetAttribute(gemm_kernel<false>,
                         cudaFuncAttributeMaxDynamicSharedMemorySize, SMEMB);
    cudaFuncSetAttribute(gemm_kernel<true>,
                         cudaFuncAttributeMaxDynamicSharedMemorySize, SMEMB);

    prep_all_kernel<<<(N_NODES + 255) / 256, 256>>>(node_emb, conv_W1,
                                                    conv_W2, conv_b2);
    hist_kernel<<<(N_EDGES + 255) / 256, 256>>>(dst);
    scan_kernel<<<SCAN_BLKS, 1024>>>();
    fill_kernel<<<(N_EDGES + 255) / 256, 256>>>(src, dst);

    const int GATHER_BLKS = (GRID_M * 128 * 32 + 255) / 256;
    // L0 tablified: z0 -> zA.  L1: zA->zB.  L2: zB->zA.  L3: zA->(pool d_g)
    layer0_kernel<<<(N_NODES * 32 + 255) / 256, 256>>>(x, conv_b1);
    gather_kernel<false><<<GATHER_BLKS, 256>>>(0, batch);
    gemm_kernel<false><<<GRID_M, 256, SMEMB>>>(1, 1, conv_b1 + 1 * HIDDEN, batch);
    gather_kernel<false><<<GATHER_BLKS, 256>>>(1, batch);
    gemm_kernel<false><<<GRID_M, 256, SMEMB>>>(0, 2, conv_b1 + 2 * HIDDEN, batch);
    gather_kernel<true><<<GATHER_BLKS, 256>>>(0, batch);
    gemm_kernel<true><<<GRID_M, 256, SMEMB>>>(1, 3, conv_b1 + 3 * HIDDEN, batch);

    head_kernel<<<NUM_GRAPHS, 128>>>(
        conv_W2 + 3 * HIDDEN * HIDDEN, conv_b2 + 3 * HIDDEN,
        mlp_W1, mlp_b1, mlp_W2, mlp_b2, mlp_W3, mlp_b3, out);
}

// round 16
// speedup vs baseline: 1.0317x; 1.0317x over previous
#include <cuda_runtime.h>
#include <cuda_bf16.h>
#include <cstdint>

#define N_NODES   100000
#define N_EDGES   625000
#define HIDDEN    128
#define INPUT_DIM 28
#define N_LAYERS  4
#define NUM_GRAPHS 512
#define GRID_M    ((N_NODES + 127) / 128)
#define SCAN_BLKS ((N_NODES + 1023) / 1024)   // 98

// Scratch (device globals; allocation inside kernel_launch is forbidden)
// z state lives in bf16 (halves gather traffic; agg still sums in fp32)
__device__ __nv_bfloat16 d_zA[N_NODES * HIDDEN];
__device__ __nv_bfloat16 d_zB[N_NODES * HIDDEN];
__device__ float d_g[NUM_GRAPHS * HIDDEN];
__device__ int   d_gcnt[NUM_GRAPHS];
// Gathered A tiles (plain bf16), pre-swizzled in GEMM smem layout:
// [tile][chunk(2)][swz(row*128 + col*2)] bf16
__device__ __nv_bfloat16 d_aggH[GRID_M * 128 * HIDDEN];
// Composite conv weights, transposed + bf16 hi/lo split: [4 mats][n=128][k=128]
__device__ __nv_bfloat16 d_WBhi[4 * HIDDEN * HIDDEN];
__device__ __nv_bfloat16 d_WBlo[4 * HIDDEN * HIDDEN];
__device__ float d_cvec[4 * HIDDEN];   // c_l = b2_{l-1} @ W1_l (c_0 = 0)
__device__ float d_Ep[INPUT_DIM * HIDDEN];   // E' = node_emb @ W1_0 (fp32)
// CSR (by dst) machinery
__device__ int d_deg[N_NODES];
__device__ int d_rowptr[N_NODES + 1];
__device__ int d_wpos[N_NODES];
__device__ int d_csr_src[N_EDGES];
__device__ int d_bsum[SCAN_BLKS];

__device__ __forceinline__ __nv_bfloat16* sel_buf(int s) {
    return s == 0 ? d_zA : d_zB;
}

__device__ __forceinline__ uint32_t smem_u32(const void* p) {
    uint32_t a;
    asm("{ .reg .u64 t; cvta.to.shared.u64 t, %1; cvt.u32.u64 %0, t; }"
        : "=r"(a) : "l"(p));
    return a;
}
// SW128-style swizzle: XOR bits[9:7] into bits[6:4]. Apply to FULL byte offset.
__device__ __forceinline__ uint32_t swz(uint32_t b) {
    return b ^ ((b >> 3) & 0x70);
}
// unpack 4 bf16 (uint2) and accumulate into float4
__device__ __forceinline__ void acc_bf4(float4& a, uint2 u) {
    __nv_bfloat162 p0 = *reinterpret_cast<__nv_bfloat162*>(&u.x);
    __nv_bfloat162 p1 = *reinterpret_cast<__nv_bfloat162*>(&u.y);
    float2 f0 = __bfloat1622float2(p0);
    float2 f1 = __bfloat1622float2(p1);
    a.x += f0.x; a.y += f0.y; a.z += f1.x; a.w += f1.y;
}
__device__ __forceinline__ uint2 pack_bf4(float4 v) {
    uint2 u;
    __nv_bfloat162 p0 = __float22bfloat162_rn(make_float2(v.x, v.y));
    __nv_bfloat162 p1 = __float22bfloat162_rn(make_float2(v.z, v.w));
    u.x = *reinterpret_cast<uint32_t*>(&p0);
    u.y = *reinterpret_cast<uint32_t*>(&p1);
    return u;
}

// ---------------------------------------------------------------------------
// Fused prep: all zeroing + composite weights + cvec + E' table, ONE kernel.
// ---------------------------------------------------------------------------
__global__ void prep_all_kernel(const float* __restrict__ node_emb,
                                const float* __restrict__ W1,
                                const float* __restrict__ W2,
                                const float* __restrict__ b2) {
    int t = blockIdx.x * blockDim.x + threadIdx.x;
    if (t < N_NODES) d_deg[t] = 0;
    if (t < NUM_GRAPHS * HIDDEN) d_g[t] = 0.f;
    if (t < NUM_GRAPHS) d_gcnt[t] = 0;

    if (t < 49152) {
        int l = 1 + (t >> 14);
        int idx = t & 16383;
        int n = idx & 127, k = idx >> 7;
        const float* W2r = W2 + (l - 1) * HIDDEN * HIDDEN + k * HIDDEN;
        const float* W1m = W1 + l * HIDDEN * HIDDEN;
        float s = 0.f;
#pragma unroll 8
        for (int j = 0; j < HIDDEN; j++) s = fmaf(W2r[j], W1m[j * HIDDEN + n], s);
        __nv_bfloat16 hi = __float2bfloat16(s);
        d_WBhi[l * 16384 + n * 128 + k] = hi;
        d_WBlo[l * 16384 + n * 128 + k] = __float2bfloat16(s - __bfloat162float(hi));
    } else if (t < 49664) {
        int u = t - 49152;
        int l = u >> 7, n = u & 127;
        float s = 0.f;
        if (l > 0) {
            const float* b2r = b2 + (l - 1) * HIDDEN;
            const float* W1m = W1 + l * HIDDEN * HIDDEN;
#pragma unroll 8
            for (int j = 0; j < HIDDEN; j++) s = fmaf(b2r[j], W1m[j * HIDDEN + n], s);
        }
        d_cvec[u] = s;
    } else if (t < 49664 + INPUT_DIM * HIDDEN) {
        int u = t - 49664;
        int v = u >> 7, n = u & 127;
        const float* er = node_emb + v * HIDDEN;
        float s = 0.f;
#pragma unroll 8
        for (int k = 0; k < HIDDEN; k++) s = fmaf(er[k], W1[k * HIDDEN + n], s);
        d_Ep[u] = s;
    }
}

// ---------------------------------------------------------------------------
// Layer 0 (tablified): z0 = relu(E'[x_i] + sum E'[x_src] + b1_0) -> bf16.
// ---------------------------------------------------------------------------
__global__ void layer0_kernel(const int* __restrict__ x,
                              const float* __restrict__ b1) {
    int t = blockIdx.x * blockDim.x + threadIdx.x;
    int node = t >> 5;
    if (node >= N_NODES) return;
    int lane = t & 31;
    int c4 = lane << 2;

    float4 acc = *(const float4*)&d_Ep[__ldg(&x[node]) * 128 + c4];
    int beg = __ldg(&d_rowptr[node]);
    int end = __ldg(&d_rowptr[node + 1]);
    int j = beg;
    for (; j + 4 <= end; j += 4) {
        int s0 = __ldg(&x[__ldg(&d_csr_src[j + 0])]);
        int s1 = __ldg(&x[__ldg(&d_csr_src[j + 1])]);
        int s2 = __ldg(&x[__ldg(&d_csr_src[j + 2])]);
        int s3 = __ldg(&x[__ldg(&d_csr_src[j + 3])]);
        float4 v0 = *(const float4*)&d_Ep[s0 * 128 + c4];
        float4 v1 = *(const float4*)&d_Ep[s1 * 128 + c4];
        float4 v2 = *(const float4*)&d_Ep[s2 * 128 + c4];
        float4 v3 = *(const float4*)&d_Ep[s3 * 128 + c4];
        acc.x += (v0.x + v1.x) + (v2.x + v3.x);
        acc.y += (v0.y + v1.y) + (v2.y + v3.y);
        acc.z += (v0.z + v1.z) + (v2.z + v3.z);
        acc.w += (v0.w + v1.w) + (v2.w + v3.w);
    }
    for (; j < end; j++) {
        int s = __ldg(&x[__ldg(&d_csr_src[j])]);
        float4 v = *(const float4*)&d_Ep[s * 128 + c4];
        acc.x += v.x; acc.y += v.y; acc.z += v.z; acc.w += v.w;
    }
    float4 bb = *(const float4*)&b1[c4];
    float4 o;
    o.x = fmaxf(acc.x + bb.x, 0.f);
    o.y = fmaxf(acc.y + bb.y, 0.f);
    o.z = fmaxf(acc.z + bb.z, 0.f);
    o.w = fmaxf(acc.w + bb.w, 0.f);
    *(uint2*)&d_zA[node * 128 + c4] = pack_bf4(o);
}

// ---------------------------------------------------------------------------
// Gather: one warp per node. agg = z[node] + sum z[src] (bf16 in, fp32 acc);
// round to bf16; write d_aggH in the GEMM smem tile layout.
// Rows beyond N_NODES (tail tile) are zero-filled. COUNT also tallies d_gcnt.
// ---------------------------------------------------------------------------
template <bool COUNT>
__global__ void gather_kernel(int insel, const int* __restrict__ batch) {
    int t = blockIdx.x * blockDim.x + threadIdx.x;
    int node = t >> 5;
    if (node >= GRID_M * 128) return;
    int lane = t & 31;
    const __nv_bfloat16* __restrict__ SRC = sel_buf(insel);
    int c4 = lane << 2;

    float4 acc = make_float4(0.f, 0.f, 0.f, 0.f);
    if (node < N_NODES) {
        if (COUNT && lane == 0) atomicAdd(&d_gcnt[__ldg(&batch[node])], 1);
        acc_bf4(acc, *(const uint2*)&SRC[node * 128 + c4]);
        int beg = __ldg(&d_rowptr[node]);
        int end = __ldg(&d_rowptr[node + 1]);
        int j = beg;
        for (; j + 4 <= end; j += 4) {
            int s0 = __ldg(&d_csr_src[j + 0]);
            int s1 = __ldg(&d_csr_src[j + 1]);
            int s2 = __ldg(&d_csr_src[j + 2]);
            int s3 = __ldg(&d_csr_src[j + 3]);
            uint2 u0 = *(const uint2*)&SRC[s0 * 128 + c4];
            uint2 u1 = *(const uint2*)&SRC[s1 * 128 + c4];
            uint2 u2 = *(const uint2*)&SRC[s2 * 128 + c4];
            uint2 u3 = *(const uint2*)&SRC[s3 * 128 + c4];
            acc_bf4(acc, u0); acc_bf4(acc, u1);
            acc_bf4(acc, u2); acc_bf4(acc, u3);
        }
        for (; j < end; j++) {
            int s = __ldg(&d_csr_src[j]);
            acc_bf4(acc, *(const uint2*)&SRC[s * 128 + c4]);
        }
    }
    int tile = node >> 7, row = node & 127;
    uint32_t off = (uint32_t)tile * 32768 + (uint32_t)(c4 >> 6) * 16384 +
                   swz((uint32_t)(row * 128) + (uint32_t)((c4 & 63) << 1));
    *(uint2*)((char*)d_aggH + off) = pack_bf4(acc);
}

// ---------------------------------------------------------------------------
// MMA helpers
// ---------------------------------------------------------------------------
__device__ __forceinline__ void mma_bf16(float* c, const uint32_t* a,
                                         const uint32_t* b) {
    asm volatile(
        "mma.sync.aligned.m16n8k16.row.col.f32.bf16.bf16.f32 "
        "{%0,%1,%2,%3}, {%4,%5,%6,%7}, {%8,%9}, {%0,%1,%2,%3};"
        : "+f"(c[0]), "+f"(c[1]), "+f"(c[2]), "+f"(c[3])
        : "r"(a[0]), "r"(a[1]), "r"(a[2]), "r"(a[3]), "r"(b[0]), "r"(b[1]));
}
#define LDSM_X4(r, addr) \
    asm volatile("ldmatrix.sync.aligned.m8n8.x4.shared.b16 {%0,%1,%2,%3}, [%4];" \
                 : "=r"((r)[0]), "=r"((r)[1]), "=r"((r)[2]), "=r"((r)[3]) \
                 : "r"(addr))
#define LDSM_X2(r, addr) \
    asm volatile("ldmatrix.sync.aligned.m8n8.x2.shared.b16 {%0,%1}, [%2];" \
                 : "=r"((r)[0]), "=r"((r)[1]) : "r"(addr))

// smem: A (2 chunks) at 0 (32KB), W-hi at 32K (16KB), W-lo at 48K. Total 64KB.
#define SW_HI 32768
#define SW_LO 49152
#define SMEMB 65536

// ---------------------------------------------------------------------------
// GEMM: y = relu(A @ WT + deg'*c + b1).  A plain bf16; W split hi/lo (2 terms).
// POOL=false: y -> zout (bf16).  POOL=true: y pooled into d_g via red.add.
// CTA: 128 rows, 256 threads (8 warps, 32x64 tiles).  [R14 proven shape]
// ---------------------------------------------------------------------------
template <bool POOL>
__global__ __launch_bounds__(256, 2) void gemm_kernel(
    int outsel, int widx, const float* __restrict__ b1,
    const int* __restrict__ batch) {
    __nv_bfloat16* __restrict__ zout = sel_buf(outsel);
    const float* __restrict__ cvec = d_cvec + widx * HIDDEN;
    const __nv_bfloat16* __restrict__ Whi = d_WBhi + widx * 16384;
    const __nv_bfloat16* __restrict__ Wlo = d_WBlo + widx * 16384;

    extern __shared__ char sm[];
    uint32_t sbase = smem_u32(sm);

    int tid = threadIdx.x;
    int lane = tid & 31;
    int wid = tid >> 5;
    int wm = (wid & 3) * 32;
    int wn = (wid >> 2) * 64;
    int bm = blockIdx.x * 128;

    // ---- A copy: identity, already swizzled in global (32KB = 2048 uint4) ----
    {
        const uint4* gh = (const uint4*)(d_aggH + (size_t)blockIdx.x * 16384);
#pragma unroll
        for (int it = 0; it < 8; it++) {
            int idx = it * 256 + tid;
            ((uint4*)sm)[idx] = gh[idx];
        }
    }

    float acc[2][8][4];
#pragma unroll
    for (int i = 0; i < 2; i++)
#pragma unroll
        for (int j = 0; j < 8; j++)
#pragma unroll
            for (int q = 0; q < 4; q++) acc[i][j][q] = 0.f;

#pragma unroll 1
    for (int ch = 0; ch < 2; ch++) {
        if (ch) __syncthreads();   // protect W overwrite
#pragma unroll
        for (int it = 0; it < 4; it++) {
            int idx = it * 256 + tid;
            int row = idx >> 3;
            int c8 = (idx & 7) * 8;
            uint32_t off = swz(row * 128 + c8 * 2);
            *(uint4*)(sm + SW_HI + off) =
                *(const uint4*)&Whi[row * 128 + ch * 64 + c8];
            *(uint4*)(sm + SW_LO + off) =
                *(const uint4*)&Wlo[row * 128 + ch * 64 + c8];
        }
        __syncthreads();
#pragma unroll
        for (int ks = 0; ks < 4; ks++) {
            uint32_t ahi[2][4];
#pragma unroll
            for (int mi = 0; mi < 2; mi++) {
                int r = wm + mi * 16 + (lane & 15);
                int kc = ks * 16 + (lane >> 4) * 8;
                uint32_t ad = sbase + (uint32_t)ch * 16384 +
                              swz((uint32_t)(r * 128 + kc * 2));
                LDSM_X4(ahi[mi], ad);
            }
#pragma unroll
            for (int nj = 0; nj < 8; nj++) {
                int nr = wn + nj * 8 + (lane & 7);
                int kc = ks * 16 + ((lane >> 3) & 1) * 8;
                uint32_t bd = sbase + SW_HI + swz((uint32_t)(nr * 128 + kc * 2));
                uint32_t bh[2], bl[2];
                LDSM_X2(bh, bd);
                LDSM_X2(bl, bd + (SW_LO - SW_HI));
#pragma unroll
                for (int mi = 0; mi < 2; mi++) {
                    mma_bf16(acc[mi][nj], ahi[mi], bh);
                    mma_bf16(acc[mi][nj], ahi[mi], bl);
                }
            }
        }
    }

    // ---- epilogue: y = relu(acc + deg'*c + b1) -> zout(bf16) OR pooled d_g ----
    int g = lane >> 2, tg = lane & 3;
    float degp[2][2];
    int gidx[2][2];
#pragma unroll
    for (int mi = 0; mi < 2; mi++)
#pragma unroll
        for (int h = 0; h < 2; h++) {
            int row = bm + wm + mi * 16 + g + h * 8;
            bool ok = row < N_NODES;
            degp[mi][h] = ok
                ? (float)(__ldg(&d_rowptr[row + 1]) - __ldg(&d_rowptr[row]) + 1)
                : 0.f;
            if (POOL) gidx[mi][h] = ok ? __ldg(&batch[row]) : 0;
        }
#pragma unroll
    for (int nj = 0; nj < 8; nj++) {
        int col = wn + nj * 8 + tg * 2;
        float2 bb = *(const float2*)&b1[col];
        float2 cv = *(const float2*)&cvec[col];
#pragma unroll
        for (int mi = 0; mi < 2; mi++) {
            int r0 = bm + wm + mi * 16 + g;
            float2 o0, o1;
            o0.x = fmaxf(acc[mi][nj][0] + degp[mi][0] * cv.x + bb.x, 0.f);
            o0.y = fmaxf(acc[mi][nj][1] + degp[mi][0] * cv.y + bb.y, 0.f);
            o1.x = fmaxf(acc[mi][nj][2] + degp[mi][1] * cv.x + bb.x, 0.f);
            o1.y = fmaxf(acc[mi][nj][3] + degp[mi][1] * cv.y + bb.y, 0.f);
            if (POOL) {
                if (r0 < N_NODES) {
                    float* p = &d_g[gidx[mi][0] * 128 + col];
                    asm volatile("red.global.add.v2.f32 [%0], {%1,%2};"
                                 :: "l"(p), "f"(o0.x), "f"(o0.y) : "memory");
                }
                if (r0 + 8 < N_NODES) {
                    float* p = &d_g[gidx[mi][1] * 128 + col];
                    asm volatile("red.global.add.v2.f32 [%0], {%1,%2};"
                                 :: "l"(p), "f"(o1.x), "f"(o1.y) : "memory");
                }
            } else {
                if (r0 < N_NODES) {
                    __nv_bfloat162 p =
                        __float22bfloat162_rn(make_float2(o0.x, o0.y));
                    *(uint32_t*)&zout[r0 * 128 + col] =
                        *reinterpret_cast<uint32_t*>(&p);
                }
                if (r0 + 8 < N_NODES) {
                    __nv_bfloat162 p =
                        __float22bfloat162_rn(make_float2(o1.x, o1.y));
                    *(uint32_t*)&zout[(r0 + 8) * 128 + col] =
                        *reinterpret_cast<uint32_t*>(&p);
                }
            }
        }
    }
}

// ---------------------------------------------------------------------------
// CSR build (by dst): histogram -> 2-phase scan -> fill
// hist/fill: 4 edges per thread (int4 loads) for atomic-latency hiding.
// ---------------------------------------------------------------------------
__global__ void hist_kernel(const int* __restrict__ dst) {
    int e0 = (blockIdx.x * blockDim.x + threadIdx.x) * 4;
    if (e0 >= N_EDGES) return;                 // N_EDGES % 4 == 0
    int4 d4 = *(const int4*)&dst[e0];
    atomicAdd(&d_deg[d4.x], 1);
    atomicAdd(&d_deg[d4.y], 1);
    atomicAdd(&d_deg[d4.z], 1);
    atomicAdd(&d_deg[d4.w], 1);
}
__global__ __launch_bounds__(1024) void scanA_kernel() {
    __shared__ int ws[32];
    int i = blockIdx.x * 1024 + threadIdx.x;
    int v = (i < N_NODES) ? d_deg[i] : 0;
    int lane = threadIdx.x & 31, w = threadIdx.x >> 5;
#pragma unroll
    for (int o = 16; o; o >>= 1) v += __shfl_down_sync(0xffffffffu, v, o);
    if (lane == 0) ws[w] = v;
    __syncthreads();
    if (w == 0) {
        int s = ws[lane];
#pragma unroll
        for (int o = 16; o; o >>= 1) s += __shfl_down_sync(0xffffffffu, s, o);
        if (lane == 0) d_bsum[blockIdx.x] = s;
    }
}
__global__ __launch_bounds__(1024) void scanC_kernel() {
    __shared__ int ws[32];
    __shared__ int sbase_sh;
    __shared__ int part[SCAN_BLKS];
    int i = blockIdx.x * 1024 + threadIdx.x;
    int v = (i < N_NODES) ? d_deg[i] : 0;
    int lane = threadIdx.x & 31, w = threadIdx.x >> 5;
    if (threadIdx.x < SCAN_BLKS) part[threadIdx.x] = d_bsum[threadIdx.x];
    int x = v;
#pragma unroll
    for (int o = 1; o < 32; o <<= 1) {
        int y = __shfl_up_sync(0xffffffffu, x, o);
        if (lane >= o) x += y;
    }
    if (lane == 31) ws[w] = x;
    __syncthreads();
    if (threadIdx.x == 0) {
        int r = 0;
        for (int q = 0; q < SCAN_BLKS && q < blockIdx.x; q++) r += part[q];
        sbase_sh = r;
    }
    if (w == 0) {
        int y = ws[lane];
#pragma unroll
        for (int o = 1; o < 32; o <<= 1) {
            int z = __shfl_up_sync(0xffffffffu, y, o);
            if (lane >= o) y += z;
        }
        ws[lane] = y;
    }
    __syncthreads();
    int incl = x + (w ? ws[w - 1] : 0);
    int excl = sbase_sh + incl - v;
    if (i < N_NODES) {
        d_rowptr[i] = excl;
        d_wpos[i] = excl;
        if (i == N_NODES - 1) d_rowptr[N_NODES] = excl + v;
    }
}
__global__ void fill_kernel(const int* __restrict__ src,
                            const int* __restrict__ dst) {
    int e0 = (blockIdx.x * blockDim.x + threadIdx.x) * 4;
    if (e0 >= N_EDGES) return;                 // N_EDGES % 4 == 0
    int4 d4 = *(const int4*)&dst[e0];
    int4 s4 = *(const int4*)&src[e0];
    int p0 = atomicAdd(&d_wpos[d4.x], 1);
    int p1 = atomicAdd(&d_wpos[d4.y], 1);
    int p2 = atomicAdd(&d_wpos[d4.z], 1);
    int p3 = atomicAdd(&d_wpos[d4.w], 1);
    d_csr_src[p0] = s4.x;
    d_csr_src[p1] = s4.y;
    d_csr_src[p2] = s4.z;
    d_csr_src[p3] = s4.w;
}

// ---------------------------------------------------------------------------
// Head: gh = gpool @ W2_3 + cnt*b2_3 ; then 128->64(relu)->32(relu)->1
// ---------------------------------------------------------------------------
__global__ __launch_bounds__(128) void head_kernel(
    const float* __restrict__ W2c, const float* __restrict__ b2c,
    const float* __restrict__ W1, const float* __restrict__ b1,
    const float* __restrict__ W2, const float* __restrict__ b2,
    const float* __restrict__ W3, const float* __restrict__ b3,
    float* __restrict__ out) {
    __shared__ float sg[128];
    __shared__ float gh[128];
    __shared__ float s1[64];
    int g = blockIdx.x;
    int tid = threadIdx.x;

    sg[tid] = d_g[g * 128 + tid];
    __syncthreads();
    float cnt = (float)d_gcnt[g];

    float a = cnt * __ldg(&b2c[tid]);
#pragma unroll 8
    for (int k = 0; k < 128; k++) a = fmaf(sg[k], W2c[k * 128 + tid], a);
    gh[tid] = a;
    __syncthreads();

    if (tid < 64) {
        float acc = __ldg(&b1[tid]);
#pragma unroll 8
        for (int k = 0; k < 128; k++) acc = fmaf(gh[k], W1[k * 64 + tid], acc);
        s1[tid] = fmaxf(acc, 0.f);
    }
    __syncthreads();

    if (tid < 32) {
        float a2 = __ldg(&b2[tid]);
#pragma unroll 8
        for (int k = 0; k < 64; k++) a2 = fmaf(s1[k], W2[k * 32 + tid], a2);
        a2 = fmaxf(a2, 0.f);
        float t3 = a2 * __ldg(&W3[tid]);
#pragma unroll
        for (int o = 16; o; o >>= 1) t3 += __shfl_down_sync(0xffffffffu, t3, o);
        if (tid == 0) out[g] = t3 + __ldg(&b3[0]);
    }
}

// ---------------------------------------------------------------------------
extern "C" void kernel_launch(void* const* d_in, const int* in_sizes, int n_in,
                              void* d_out, int out_size) {
    const int*   x        = (const int*)d_in[0];
    const int*   edge_idx = (const int*)d_in[1];
    const int*   src      = edge_idx;
    const int*   dst      = edge_idx + N_EDGES;
    const int*   batch    = (const int*)d_in[3];
    const float* node_emb = (const float*)d_in[4];
    // d_in[2] (edge_attr) and d_in[5] (edge_emb) are dead in the reference.
    const float* conv_W1  = (const float*)d_in[6];
    const float* conv_b1  = (const float*)d_in[7];
    const float* conv_W2  = (const float*)d_in[8];
    const float* conv_b2  = (const float*)d_in[9];
    const float* mlp_W1   = (const float*)d_in[10];
    const float* mlp_b1   = (const float*)d_in[11];
    const float* mlp_W2   = (const float*)d_in[12];
    const float* mlp_b2   = (const float*)d_in[13];
    const float* mlp_W3   = (const float*)d_in[14];
    const float* mlp_b3   = (const float*)d_in[15];
    float* out = (float*)d_out;

    cudaFuncSetAttribute(gemm_kernel<false>,
                         cudaFuncAttributeMaxDynamicSharedMemorySize, SMEMB);
    cudaFuncSetAttribute(gemm_kernel<true>,
                         cudaFuncAttributeMaxDynamicSharedMemorySize, SMEMB);

    prep_all_kernel<<<(N_NODES + 255) / 256, 256>>>(node_emb, conv_W1,
                                                    conv_W2, conv_b2);
    hist_kernel<<<(N_EDGES / 4 + 255) / 256, 256>>>(dst);
    scanA_kernel<<<SCAN_BLKS, 1024>>>();
    scanC_kernel<<<SCAN_BLKS, 1024>>>();
    fill_kernel<<<(N_EDGES / 4 + 255) / 256, 256>>>(src, dst);

    const int GATHER_BLKS = (GRID_M * 128 * 32 + 255) / 256;
    // L0 tablified: z0 -> zA.  L1: zA->zB.  L2: zB->zA.  L3: zA->(pool d_g)
    layer0_kernel<<<(N_NODES * 32 + 255) / 256, 256>>>(x, conv_b1);
    gather_kernel<false><<<GATHER_BLKS, 256>>>(0, batch);
    gemm_kernel<false><<<GRID_M, 256, SMEMB>>>(1, 1, conv_b1 + 1 * HIDDEN, batch);
    gather_kernel<false><<<GATHER_BLKS, 256>>>(1, batch);
    gemm_kernel<false><<<GRID_M, 256, SMEMB>>>(0, 2, conv_b1 + 2 * HIDDEN, batch);
    gather_kernel<true><<<GATHER_BLKS, 256>>>(0, batch);
    gemm_kernel<true><<<GRID_M, 256, SMEMB>>>(1, 3, conv_b1 + 3 * HIDDEN, batch);

    head_kernel<<<NUM_GRAPHS, 128>>>(
        conv_W2 + 3 * HIDDEN * HIDDEN, conv_b2 + 3 * HIDDEN,
        mlp_W1, mlp_b1, mlp_W2, mlp_b2, mlp_W3, mlp_b3, out);
}

// round 17
// speedup vs baseline: 1.0520x; 1.0197x over previous
#include <cuda_runtime.h>
#include <cuda_bf16.h>
#include <cstdint>

#define N_NODES   100000
#define N_EDGES   625000
#define HIDDEN    128
#define INPUT_DIM 28
#define N_LAYERS  4
#define NUM_GRAPHS 512
#define GRID_M    ((N_NODES + 127) / 128)
#define SCAN_BLKS ((N_NODES + 1023) / 1024)   // 98

// Scratch (device globals; allocation inside kernel_launch is forbidden)
// z state lives in bf16 (halves gather traffic; agg still sums in fp32)
__device__ __nv_bfloat16 d_zA[N_NODES * HIDDEN];
__device__ __nv_bfloat16 d_zB[N_NODES * HIDDEN];
__device__ float d_g[NUM_GRAPHS * HIDDEN];
__device__ int   d_gcnt[NUM_GRAPHS];
// Gathered A tiles (plain bf16), pre-swizzled in GEMM smem layout:
// [tile][chunk(2)][swz(row*128 + col*2)] bf16
__device__ __nv_bfloat16 d_aggH[GRID_M * 128 * HIDDEN];
// Composite conv weights, transposed + bf16 hi/lo split: [4 mats][n=128][k=128]
__device__ __nv_bfloat16 d_WBhi[4 * HIDDEN * HIDDEN];
__device__ __nv_bfloat16 d_WBlo[4 * HIDDEN * HIDDEN];
__device__ float d_cvec[4 * HIDDEN];   // c_l = b2_{l-1} @ W1_l (c_0 = 0)
__device__ float d_Ep[INPUT_DIM * HIDDEN];   // E' = node_emb @ W1_0 (fp32)
// CSR (by dst) machinery
__device__ int d_deg[N_NODES];
__device__ int d_rowptr[N_NODES + 1];
__device__ int d_wpos[N_NODES];
__device__ int d_csr_src[N_EDGES];
__device__ int d_bsum[SCAN_BLKS];

__device__ __forceinline__ __nv_bfloat16* sel_buf(int s) {
    return s == 0 ? d_zA : d_zB;
}

__device__ __forceinline__ uint32_t smem_u32(const void* p) {
    uint32_t a;
    asm("{ .reg .u64 t; cvta.to.shared.u64 t, %1; cvt.u32.u64 %0, t; }"
        : "=r"(a) : "l"(p));
    return a;
}
// SW128-style swizzle: XOR bits[9:7] into bits[6:4]. Apply to FULL byte offset.
__device__ __forceinline__ uint32_t swz(uint32_t b) {
    return b ^ ((b >> 3) & 0x70);
}
// unpack 8 bf16 (uint4) and accumulate into float[8]
__device__ __forceinline__ void acc_bf8(float* a, uint4 u) {
    uint32_t w[4] = {u.x, u.y, u.z, u.w};
#pragma unroll
    for (int q = 0; q < 4; q++) {
        __nv_bfloat162 p = *reinterpret_cast<__nv_bfloat162*>(&w[q]);
        float2 f = __bfloat1622float2(p);
        a[q * 2 + 0] += f.x;
        a[q * 2 + 1] += f.y;
    }
}
__device__ __forceinline__ uint4 pack_bf8(const float* v) {
    uint4 u;
    uint32_t w[4];
#pragma unroll
    for (int q = 0; q < 4; q++) {
        __nv_bfloat162 p =
            __float22bfloat162_rn(make_float2(v[q * 2 + 0], v[q * 2 + 1]));
        w[q] = *reinterpret_cast<uint32_t*>(&p);
    }
    u.x = w[0]; u.y = w[1]; u.z = w[2]; u.w = w[3];
    return u;
}
__device__ __forceinline__ uint2 pack_bf4(float4 v) {
    uint2 u;
    __nv_bfloat162 p0 = __float22bfloat162_rn(make_float2(v.x, v.y));
    __nv_bfloat162 p1 = __float22bfloat162_rn(make_float2(v.z, v.w));
    u.x = *reinterpret_cast<uint32_t*>(&p0);
    u.y = *reinterpret_cast<uint32_t*>(&p1);
    return u;
}

// ---------------------------------------------------------------------------
// Fused prep: all zeroing + composite weights + cvec + E' table, ONE kernel.
// ---------------------------------------------------------------------------
__global__ void prep_all_kernel(const float* __restrict__ node_emb,
                                const float* __restrict__ W1,
                                const float* __restrict__ W2,
                                const float* __restrict__ b2) {
    int t = blockIdx.x * blockDim.x + threadIdx.x;
    if (t < N_NODES) d_deg[t] = 0;
    if (t < NUM_GRAPHS * HIDDEN) d_g[t] = 0.f;
    if (t < NUM_GRAPHS) d_gcnt[t] = 0;

    if (t < 49152) {
        int l = 1 + (t >> 14);
        int idx = t & 16383;
        int n = idx & 127, k = idx >> 7;
        const float* W2r = W2 + (l - 1) * HIDDEN * HIDDEN + k * HIDDEN;
        const float* W1m = W1 + l * HIDDEN * HIDDEN;
        float s = 0.f;
#pragma unroll 8
        for (int j = 0; j < HIDDEN; j++) s = fmaf(W2r[j], W1m[j * HIDDEN + n], s);
        __nv_bfloat16 hi = __float2bfloat16(s);
        d_WBhi[l * 16384 + n * 128 + k] = hi;
        d_WBlo[l * 16384 + n * 128 + k] = __float2bfloat16(s - __bfloat162float(hi));
    } else if (t < 49664) {
        int u = t - 49152;
        int l = u >> 7, n = u & 127;
        float s = 0.f;
        if (l > 0) {
            const float* b2r = b2 + (l - 1) * HIDDEN;
            const float* W1m = W1 + l * HIDDEN * HIDDEN;
#pragma unroll 8
            for (int j = 0; j < HIDDEN; j++) s = fmaf(b2r[j], W1m[j * HIDDEN + n], s);
        }
        d_cvec[u] = s;
    } else if (t < 49664 + INPUT_DIM * HIDDEN) {
        int u = t - 49664;
        int v = u >> 7, n = u & 127;
        const float* er = node_emb + v * HIDDEN;
        float s = 0.f;
#pragma unroll 8
        for (int k = 0; k < HIDDEN; k++) s = fmaf(er[k], W1[k * HIDDEN + n], s);
        d_Ep[u] = s;
    }
}

// ---------------------------------------------------------------------------
// Layer 0 (tablified): z0 = relu(E'[x_i] + sum E'[x_src] + b1_0) -> bf16.
// ---------------------------------------------------------------------------
__global__ void layer0_kernel(const int* __restrict__ x,
                              const float* __restrict__ b1) {
    int t = blockIdx.x * blockDim.x + threadIdx.x;
    int node = t >> 5;
    if (node >= N_NODES) return;
    int lane = t & 31;
    int c4 = lane << 2;

    float4 acc = *(const float4*)&d_Ep[__ldg(&x[node]) * 128 + c4];
    int beg = __ldg(&d_rowptr[node]);
    int end = __ldg(&d_rowptr[node + 1]);
    int j = beg;
    for (; j + 4 <= end; j += 4) {
        int s0 = __ldg(&x[__ldg(&d_csr_src[j + 0])]);
        int s1 = __ldg(&x[__ldg(&d_csr_src[j + 1])]);
        int s2 = __ldg(&x[__ldg(&d_csr_src[j + 2])]);
        int s3 = __ldg(&x[__ldg(&d_csr_src[j + 3])]);
        float4 v0 = *(const float4*)&d_Ep[s0 * 128 + c4];
        float4 v1 = *(const float4*)&d_Ep[s1 * 128 + c4];
        float4 v2 = *(const float4*)&d_Ep[s2 * 128 + c4];
        float4 v3 = *(const float4*)&d_Ep[s3 * 128 + c4];
        acc.x += (v0.x + v1.x) + (v2.x + v3.x);
        acc.y += (v0.y + v1.y) + (v2.y + v3.y);
        acc.z += (v0.z + v1.z) + (v2.z + v3.z);
        acc.w += (v0.w + v1.w) + (v2.w + v3.w);
    }
    for (; j < end; j++) {
        int s = __ldg(&x[__ldg(&d_csr_src[j])]);
        float4 v = *(const float4*)&d_Ep[s * 128 + c4];
        acc.x += v.x; acc.y += v.y; acc.z += v.z; acc.w += v.w;
    }
    float4 bb = *(const float4*)&b1[c4];
    float4 o;
    o.x = fmaxf(acc.x + bb.x, 0.f);
    o.y = fmaxf(acc.y + bb.y, 0.f);
    o.z = fmaxf(acc.z + bb.z, 0.f);
    o.w = fmaxf(acc.w + bb.w, 0.f);
    *(uint2*)&d_zA[node * 128 + c4] = pack_bf4(o);
}

// ---------------------------------------------------------------------------
// Gather: HALF-WARP per node (lane covers 16B = 8 bf16 of the 256B row).
// Two independent nodes per warp -> 2x independent load streams.
// agg = z[node] + sum z[src] (bf16 in, fp32 acc) -> bf16 tile write.
// Rows beyond N_NODES (tail tile) are zero-filled. COUNT also tallies d_gcnt.
// ---------------------------------------------------------------------------
template <bool COUNT>
__global__ void gather_kernel(int insel, const int* __restrict__ batch) {
    int t = blockIdx.x * blockDim.x + threadIdx.x;
    int node = t >> 4;
    if (node >= GRID_M * 128) return;
    int l16 = t & 15;
    const __nv_bfloat16* __restrict__ SRC = sel_buf(insel);
    int c8 = l16 << 3;                    // 8 bf16 columns per lane

    float acc[8] = {0.f, 0.f, 0.f, 0.f, 0.f, 0.f, 0.f, 0.f};
    if (node < N_NODES) {
        if (COUNT && l16 == 0) atomicAdd(&d_gcnt[__ldg(&batch[node])], 1);
        acc_bf8(acc, *(const uint4*)&SRC[node * 128 + c8]);
        int beg = __ldg(&d_rowptr[node]);
        int end = __ldg(&d_rowptr[node + 1]);
        int j = beg;
        for (; j + 4 <= end; j += 4) {
            int s0 = __ldg(&d_csr_src[j + 0]);
            int s1 = __ldg(&d_csr_src[j + 1]);
            int s2 = __ldg(&d_csr_src[j + 2]);
            int s3 = __ldg(&d_csr_src[j + 3]);
            uint4 u0 = *(const uint4*)&SRC[s0 * 128 + c8];
            uint4 u1 = *(const uint4*)&SRC[s1 * 128 + c8];
            uint4 u2 = *(const uint4*)&SRC[s2 * 128 + c8];
            uint4 u3 = *(const uint4*)&SRC[s3 * 128 + c8];
            acc_bf8(acc, u0); acc_bf8(acc, u1);
            acc_bf8(acc, u2); acc_bf8(acc, u3);
        }
        for (; j < end; j++) {
            int s = __ldg(&d_csr_src[j]);
            acc_bf8(acc, *(const uint4*)&SRC[s * 128 + c8]);
        }
    }
    int tile = node >> 7, row = node & 127;
    uint32_t off = (uint32_t)tile * 32768 + (uint32_t)(c8 >> 6) * 16384 +
                   swz((uint32_t)(row * 128) + (uint32_t)((c8 & 63) << 1));
    *(uint4*)((char*)d_aggH + off) = pack_bf8(acc);
}

// ---------------------------------------------------------------------------
// MMA helpers
// ---------------------------------------------------------------------------
__device__ __forceinline__ void mma_bf16(float* c, const uint32_t* a,
                                         const uint32_t* b) {
    asm volatile(
        "mma.sync.aligned.m16n8k16.row.col.f32.bf16.bf16.f32 "
        "{%0,%1,%2,%3}, {%4,%5,%6,%7}, {%8,%9}, {%0,%1,%2,%3};"
        : "+f"(c[0]), "+f"(c[1]), "+f"(c[2]), "+f"(c[3])
        : "r"(a[0]), "r"(a[1]), "r"(a[2]), "r"(a[3]), "r"(b[0]), "r"(b[1]));
}
#define LDSM_X4(r, addr) \
    asm volatile("ldmatrix.sync.aligned.m8n8.x4.shared.b16 {%0,%1,%2,%3}, [%4];" \
                 : "=r"((r)[0]), "=r"((r)[1]), "=r"((r)[2]), "=r"((r)[3]) \
                 : "r"(addr))
#define LDSM_X2(r, addr) \
    asm volatile("ldmatrix.sync.aligned.m8n8.x2.shared.b16 {%0,%1}, [%2];" \
                 : "=r"((r)[0]), "=r"((r)[1]) : "r"(addr))

// smem: A (2 chunks) at 0 (32KB), W-hi at 32K (16KB), W-lo at 48K. Total 64KB.
#define SW_HI 32768
#define SW_LO 49152
#define SMEMB 65536

// ---------------------------------------------------------------------------
// GEMM: y = relu(A @ WT + deg'*c + b1).  A plain bf16; W split hi/lo (2 terms).
// POOL=false: y -> zout (bf16).  POOL=true: y pooled into d_g via red.add.
// CTA: 128 rows, 256 threads (8 warps, 32x64 tiles).  [R14 proven shape]
// ---------------------------------------------------------------------------
template <bool POOL>
__global__ __launch_bounds__(256, 2) void gemm_kernel(
    int outsel, int widx, const float* __restrict__ b1,
    const int* __restrict__ batch) {
    __nv_bfloat16* __restrict__ zout = sel_buf(outsel);
    const float* __restrict__ cvec = d_cvec + widx * HIDDEN;
    const __nv_bfloat16* __restrict__ Whi = d_WBhi + widx * 16384;
    const __nv_bfloat16* __restrict__ Wlo = d_WBlo + widx * 16384;

    extern __shared__ char sm[];
    uint32_t sbase = smem_u32(sm);

    int tid = threadIdx.x;
    int lane = tid & 31;
    int wid = tid >> 5;
    int wm = (wid & 3) * 32;
    int wn = (wid >> 2) * 64;
    int bm = blockIdx.x * 128;

    // ---- A copy: identity, already swizzled in global (32KB = 2048 uint4) ----
    {
        const uint4* gh = (const uint4*)(d_aggH + (size_t)blockIdx.x * 16384);
#pragma unroll
        for (int it = 0; it < 8; it++) {
            int idx = it * 256 + tid;
            ((uint4*)sm)[idx] = gh[idx];
        }
    }

    float acc[2][8][4];
#pragma unroll
    for (int i = 0; i < 2; i++)
#pragma unroll
        for (int j = 0; j < 8; j++)
#pragma unroll
            for (int q = 0; q < 4; q++) acc[i][j][q] = 0.f;

#pragma unroll 1
    for (int ch = 0; ch < 2; ch++) {
        if (ch) __syncthreads();   // protect W overwrite
#pragma unroll
        for (int it = 0; it < 4; it++) {
            int idx = it * 256 + tid;
            int row = idx >> 3;
            int c8 = (idx & 7) * 8;
            uint32_t off = swz(row * 128 + c8 * 2);
            *(uint4*)(sm + SW_HI + off) =
                *(const uint4*)&Whi[row * 128 + ch * 64 + c8];
            *(uint4*)(sm + SW_LO + off) =
                *(const uint4*)&Wlo[row * 128 + ch * 64 + c8];
        }
        __syncthreads();
#pragma unroll
        for (int ks = 0; ks < 4; ks++) {
            uint32_t ahi[2][4];
#pragma unroll
            for (int mi = 0; mi < 2; mi++) {
                int r = wm + mi * 16 + (lane & 15);
                int kc = ks * 16 + (lane >> 4) * 8;
                uint32_t ad = sbase + (uint32_t)ch * 16384 +
                              swz((uint32_t)(r * 128 + kc * 2));
                LDSM_X4(ahi[mi], ad);
            }
#pragma unroll
            for (int nj = 0; nj < 8; nj++) {
                int nr = wn + nj * 8 + (lane & 7);
                int kc = ks * 16 + ((lane >> 3) & 1) * 8;
                uint32_t bd = sbase + SW_HI + swz((uint32_t)(nr * 128 + kc * 2));
                uint32_t bh[2], bl[2];
                LDSM_X2(bh, bd);
                LDSM_X2(bl, bd + (SW_LO - SW_HI));
#pragma unroll
                for (int mi = 0; mi < 2; mi++) {
                    mma_bf16(acc[mi][nj], ahi[mi], bh);
                    mma_bf16(acc[mi][nj], ahi[mi], bl);
                }
            }
        }
    }

    // ---- epilogue: y = relu(acc + deg'*c + b1) -> zout(bf16) OR pooled d_g ----
    int g = lane >> 2, tg = lane & 3;
    float degp[2][2];
    int gidx[2][2];
#pragma unroll
    for (int mi = 0; mi < 2; mi++)
#pragma unroll
        for (int h = 0; h < 2; h++) {
            int row = bm + wm + mi * 16 + g + h * 8;
            bool ok = row < N_NODES;
            degp[mi][h] = ok
                ? (float)(__ldg(&d_rowptr[row + 1]) - __ldg(&d_rowptr[row]) + 1)
                : 0.f;
            if (POOL) gidx[mi][h] = ok ? __ldg(&batch[row]) : 0;
        }
#pragma unroll
    for (int nj = 0; nj < 8; nj++) {
        int col = wn + nj * 8 + tg * 2;
        float2 bb = *(const float2*)&b1[col];
        float2 cv = *(const float2*)&cvec[col];
#pragma unroll
        for (int mi = 0; mi < 2; mi++) {
            int r0 = bm + wm + mi * 16 + g;
            float2 o0, o1;
            o0.x = fmaxf(acc[mi][nj][0] + degp[mi][0] * cv.x + bb.x, 0.f);
            o0.y = fmaxf(acc[mi][nj][1] + degp[mi][0] * cv.y + bb.y, 0.f);
            o1.x = fmaxf(acc[mi][nj][2] + degp[mi][1] * cv.x + bb.x, 0.f);
            o1.y = fmaxf(acc[mi][nj][3] + degp[mi][1] * cv.y + bb.y, 0.f);
            if (POOL) {
                if (r0 < N_NODES) {
                    float* p = &d_g[gidx[mi][0] * 128 + col];
                    asm volatile("red.global.add.v2.f32 [%0], {%1,%2};"
                                 :: "l"(p), "f"(o0.x), "f"(o0.y) : "memory");
                }
                if (r0 + 8 < N_NODES) {
                    float* p = &d_g[gidx[mi][1] * 128 + col];
                    asm volatile("red.global.add.v2.f32 [%0], {%1,%2};"
                                 :: "l"(p), "f"(o1.x), "f"(o1.y) : "memory");
                }
            } else {
                if (r0 < N_NODES) {
                    __nv_bfloat162 p =
                        __float22bfloat162_rn(make_float2(o0.x, o0.y));
                    *(uint32_t*)&zout[r0 * 128 + col] =
                        *reinterpret_cast<uint32_t*>(&p);
                }
                if (r0 + 8 < N_NODES) {
                    __nv_bfloat162 p =
                        __float22bfloat162_rn(make_float2(o1.x, o1.y));
                    *(uint32_t*)&zout[(r0 + 8) * 128 + col] =
                        *reinterpret_cast<uint32_t*>(&p);
                }
            }
        }
    }
}

// ---------------------------------------------------------------------------
// CSR build (by dst): histogram -> 2-phase scan -> fill (4 edges/thread)
// ---------------------------------------------------------------------------
__global__ void hist_kernel(const int* __restrict__ dst) {
    int e0 = (blockIdx.x * blockDim.x + threadIdx.x) * 4;
    if (e0 >= N_EDGES) return;                 // N_EDGES % 4 == 0
    int4 d4 = *(const int4*)&dst[e0];
    atomicAdd(&d_deg[d4.x], 1);
    atomicAdd(&d_deg[d4.y], 1);
    atomicAdd(&d_deg[d4.z], 1);
    atomicAdd(&d_deg[d4.w], 1);
}
__global__ __launch_bounds__(1024) void scanA_kernel() {
    __shared__ int ws[32];
    int i = blockIdx.x * 1024 + threadIdx.x;
    int v = (i < N_NODES) ? d_deg[i] : 0;
    int lane = threadIdx.x & 31, w = threadIdx.x >> 5;
#pragma unroll
    for (int o = 16; o; o >>= 1) v += __shfl_down_sync(0xffffffffu, v, o);
    if (lane == 0) ws[w] = v;
    __syncthreads();
    if (w == 0) {
        int s = ws[lane];
#pragma unroll
        for (int o = 16; o; o >>= 1) s += __shfl_down_sync(0xffffffffu, s, o);
        if (lane == 0) d_bsum[blockIdx.x] = s;
    }
}
__global__ __launch_bounds__(1024) void scanC_kernel() {
    __shared__ int ws[32];
    __shared__ int sbase_sh;
    __shared__ int part[SCAN_BLKS];
    int i = blockIdx.x * 1024 + threadIdx.x;
    int v = (i < N_NODES) ? d_deg[i] : 0;
    int lane = threadIdx.x & 31, w = threadIdx.x >> 5;
    if (threadIdx.x < SCAN_BLKS) part[threadIdx.x] = d_bsum[threadIdx.x];
    int x = v;
#pragma unroll
    for (int o = 1; o < 32; o <<= 1) {
        int y = __shfl_up_sync(0xffffffffu, x, o);
        if (lane >= o) x += y;
    }
    if (lane == 31) ws[w] = x;
    __syncthreads();
    if (threadIdx.x == 0) {
        int r = 0;
        for (int q = 0; q < SCAN_BLKS && q < blockIdx.x; q++) r += part[q];
        sbase_sh = r;
    }
    if (w == 0) {
        int y = ws[lane];
#pragma unroll
        for (int o = 1; o < 32; o <<= 1) {
            int z = __shfl_up_sync(0xffffffffu, y, o);
            if (lane >= o) y += z;
        }
        ws[lane] = y;
    }
    __syncthreads();
    int incl = x + (w ? ws[w - 1] : 0);
    int excl = sbase_sh + incl - v;
    if (i < N_NODES) {
        d_rowptr[i] = excl;
        d_wpos[i] = excl;
        if (i == N_NODES - 1) d_rowptr[N_NODES] = excl + v;
    }
}
__global__ void fill_kernel(const int* __restrict__ src,
                            const int* __restrict__ dst) {
    int e0 = (blockIdx.x * blockDim.x + threadIdx.x) * 4;
    if (e0 >= N_EDGES) return;                 // N_EDGES % 4 == 0
    int4 d4 = *(const int4*)&dst[e0];
    int4 s4 = *(const int4*)&src[e0];
    int p0 = atomicAdd(&d_wpos[d4.x], 1);
    int p1 = atomicAdd(&d_wpos[d4.y], 1);
    int p2 = atomicAdd(&d_wpos[d4.z], 1);
    int p3 = atomicAdd(&d_wpos[d4.w], 1);
    d_csr_src[p0] = s4.x;
    d_csr_src[p1] = s4.y;
    d_csr_src[p2] = s4.z;
    d_csr_src[p3] = s4.w;
}

// ---------------------------------------------------------------------------
// Head: gh = gpool @ W2_3 + cnt*b2_3 ; then 128->64(relu)->32(relu)->1
// ---------------------------------------------------------------------------
__global__ __launch_bounds__(128) void head_kernel(
    const float* __restrict__ W2c, const float* __restrict__ b2c,
    const float* __restrict__ W1, const float* __restrict__ b1,
    const float* __restrict__ W2, const float* __restrict__ b2,
    const float* __restrict__ W3, const float* __restrict__ b3,
    float* __restrict__ out) {
    __shared__ float sg[128];
    __shared__ float gh[128];
    __shared__ float s1[64];
    int g = blockIdx.x;
    int tid = threadIdx.x;

    sg[tid] = d_g[g * 128 + tid];
    __syncthreads();
    float cnt = (float)d_gcnt[g];

    float a = cnt * __ldg(&b2c[tid]);
#pragma unroll 8
    for (int k = 0; k < 128; k++) a = fmaf(sg[k], W2c[k * 128 + tid], a);
    gh[tid] = a;
    __syncthreads();

    if (tid < 64) {
        float acc = __ldg(&b1[tid]);
#pragma unroll 8
        for (int k = 0; k < 128; k++) acc = fmaf(gh[k], W1[k * 64 + tid], acc);
        s1[tid] = fmaxf(acc, 0.f);
    }
    __syncthreads();

    if (tid < 32) {
        float a2 = __ldg(&b2[tid]);
#pragma unroll 8
        for (int k = 0; k < 64; k++) a2 = fmaf(s1[k], W2[k * 32 + tid], a2);
        a2 = fmaxf(a2, 0.f);
        float t3 = a2 * __ldg(&W3[tid]);
#pragma unroll
        for (int o = 16; o; o >>= 1) t3 += __shfl_down_sync(0xffffffffu, t3, o);
        if (tid == 0) out[g] = t3 + __ldg(&b3[0]);
    }
}

// ---------------------------------------------------------------------------
extern "C" void kernel_launch(void* const* d_in, const int* in_sizes, int n_in,
                              void* d_out, int out_size) {
    const int*   x        = (const int*)d_in[0];
    const int*   edge_idx = (const int*)d_in[1];
    const int*   src      = edge_idx;
    const int*   dst      = edge_idx + N_EDGES;
    const int*   batch    = (const int*)d_in[3];
    const float* node_emb = (const float*)d_in[4];
    // d_in[2] (edge_attr) and d_in[5] (edge_emb) are dead in the reference.
    const float* conv_W1  = (const float*)d_in[6];
    const float* conv_b1  = (const float*)d_in[7];
    const float* conv_W2  = (const float*)d_in[8];
    const float* conv_b2  = (const float*)d_in[9];
    const float* mlp_W1   = (const float*)d_in[10];
    const float* mlp_b1   = (const float*)d_in[11];
    const float* mlp_W2   = (const float*)d_in[12];
    const float* mlp_b2   = (const float*)d_in[13];
    const float* mlp_W3   = (const float*)d_in[14];
    const float* mlp_b3   = (const float*)d_in[15];
    float* out = (float*)d_out;

    cudaFuncSetAttribute(gemm_kernel<false>,
                         cudaFuncAttributeMaxDynamicSharedMemorySize, SMEMB);
    cudaFuncSetAttribute(gemm_kernel<true>,
                         cudaFuncAttributeMaxDynamicSharedMemorySize, SMEMB);

    prep_all_kernel<<<(N_NODES + 255) / 256, 256>>>(node_emb, conv_W1,
                                                    conv_W2, conv_b2);
    hist_kernel<<<(N_EDGES / 4 + 255) / 256, 256>>>(dst);
    scanA_kernel<<<SCAN_BLKS, 1024>>>();
    scanC_kernel<<<SCAN_BLKS, 1024>>>();
    fill_kernel<<<(N_EDGES / 4 + 255) / 256, 256>>>(src, dst);

    const int GATHER_BLKS = (GRID_M * 128 * 16 + 255) / 256;
    // L0 tablified: z0 -> zA.  L1: zA->zB.  L2: zB->zA.  L3: zA->(pool d_g)
    layer0_kernel<<<(N_NODES * 32 + 255) / 256, 256>>>(x, conv_b1);
    gather_kernel<false><<<GATHER_BLKS, 256>>>(0, batch);
    gemm_kernel<false><<<GRID_M, 256, SMEMB>>>(1, 1, conv_b1 + 1 * HIDDEN, batch);
    gather_kernel<false><<<GATHER_BLKS, 256>>>(1, batch);
    gemm_kernel<false><<<GRID_M, 256, SMEMB>>>(0, 2, conv_b1 + 2 * HIDDEN, batch);
    gather_kernel<true><<<GATHER_BLKS, 256>>>(0, batch);
    gemm_kernel<true><<<GRID_M, 256, SMEMB>>>(1, 3, conv_b1 + 3 * HIDDEN, batch);

    head_kernel<<<NUM_GRAPHS, 128>>>(
        conv_W2 + 3 * HIDDEN * HIDDEN, conv_b2 + 3 * HIDDEN,
        mlp_W1, mlp_b1, mlp_W2, mlp_b2, mlp_W3, mlp_b3, out);
}